// round 7
// baseline (speedup 1.0000x reference)
#include <cuda_runtime.h>
#include <math.h>

#define NPART 4096
#define NC 16

#define R_ON2  (1.7f * 1.7f)       /* 2.89  */
#define R_C2   (4.0f)              /* 2.0^2 */
#define CUT_INV_DENOM (1.0f / ((R_C2 - R_ON2) * (R_C2 - R_ON2) * (R_C2 - R_ON2)))
#define ALPHA_F 2.8f

#define NCELL_DIM 16
#define NCELLS (NCELL_DIM * NCELL_DIM * NCELL_DIM)   /* 4096 */
#define INV_CELLW 0.4f                               /* 1 / 2.5 */

#define EBLOCKS 144                                  /* 4096*9/256 */

// scratch (no allocations; zero-initialized at load; all counters return to
// zero by end of each launch -> graph replays see identical initial state)
__device__ float  g_w[NPART * NC];    // w_i[d] = 0.5*sum_c ct[c]*(E[c,d]+E[d,c])
__device__ float  g_mask[NPART];      // column mask: sum(ct_j) > 0
__device__ float4 g_pos4[NPART];      // x,y,z,radius
__device__ int    g_cellid[NPART];
__device__ int    g_cnt[NCELLS];      // histogram; scatter drains back to 0
__device__ int    g_start[NCELLS + 1];
__device__ int    g_sortedidx[NPART]; // particle ids, cell-grouped, ascending
__device__ float4 s_pos4[NPART];      // slot-indexed gathered copies
__device__ float  s_mask[NPART];
__device__ int    s_cell[NPART];
__device__ float  g_part[EBLOCKS];
__device__ unsigned int g_count;

// ---------------------------------------------------------------------------
// Kernel 1: per-particle contraction w_i = ct_i^T E_sym_i, mask, pos4 pack,
// cell binning. One thread per (particle, dim).
// ---------------------------------------------------------------------------
__global__ __launch_bounds__(128)
void prep_kernel(const float* __restrict__ pos,
                 const float* __restrict__ ct,
                 const float* __restrict__ E,
                 const float* __restrict__ rad) {
    const int t = blockIdx.x * 128 + threadIdx.x;   // 0 .. 65535
    const int i = t >> 4;
    const int d = t & 15;

    const float4* __restrict__ ct4 = (const float4*)(ct + i * NC);
    float4 c0 = ct4[0], c1 = ct4[1], c2 = ct4[2], c3 = ct4[3];
    float sct[16] = {c0.x, c0.y, c0.z, c0.w, c1.x, c1.y, c1.z, c1.w,
                     c2.x, c2.y, c2.z, c2.w, c3.x, c3.y, c3.z, c3.w};

    const float4* __restrict__ Er4 = (const float4*)(E + i * 256 + d * NC);
    float4 r0 = Er4[0], r1 = Er4[1], r2 = Er4[2], r3 = Er4[3];
    float er[16] = {r0.x, r0.y, r0.z, r0.w, r1.x, r1.y, r1.z, r1.w,
                    r2.x, r2.y, r2.z, r2.w, r3.x, r3.y, r3.z, r3.w};

    const float* __restrict__ Ec = E + i * 256 + d;
    float w = 0.0f;
#pragma unroll
    for (int c = 0; c < 16; c++) {
        w = fmaf(sct[c], er[c] + __ldg(Ec + c * 16), w);
    }
    g_w[t] = 0.5f * w;

    if (d == 0) {
        float s = 0.0f;
#pragma unroll
        for (int c = 0; c < 16; c++) s += sct[c];
        g_mask[i] = (s > 0.0f) ? 1.0f : 0.0f;
        float px = pos[3 * i], py = pos[3 * i + 1], pz = pos[3 * i + 2];
        g_pos4[i] = make_float4(px, py, pz, rad[i]);
        int cx = min((int)(px * INV_CELLW), NCELL_DIM - 1);
        int cy = min((int)(py * INV_CELLW), NCELL_DIM - 1);
        int cz = min((int)(pz * INV_CELLW), NCELL_DIM - 1);
        int cell = (cz << 8) | (cy << 4) | cx;
        g_cellid[i] = cell;
        atomicAdd(&g_cnt[cell], 1);
    }
}

// ---------------------------------------------------------------------------
// Kernel 2: exclusive scan of 4096 cell counts. One block, 1024 threads,
// shfl-based (2 barriers total).
// ---------------------------------------------------------------------------
__global__ __launch_bounds__(1024)
void scan_kernel() {
    __shared__ int wsum[32];
    const int tid = threadIdx.x, lane = tid & 31, wp = tid >> 5;
    int a = g_cnt[4 * tid + 0];
    int b = g_cnt[4 * tid + 1];
    int c = g_cnt[4 * tid + 2];
    int d = g_cnt[4 * tid + 3];
    int sum = a + b + c + d;
    int x = sum;
#pragma unroll
    for (int off = 1; off < 32; off <<= 1) {
        int y = __shfl_up_sync(0xffffffffu, x, off);
        if (lane >= off) x += y;
    }
    if (lane == 31) wsum[wp] = x;
    __syncthreads();
    if (wp == 0) {
        int v = wsum[lane];
#pragma unroll
        for (int off = 1; off < 32; off <<= 1) {
            int y = __shfl_up_sync(0xffffffffu, v, off);
            if (lane >= off) v += y;
        }
        wsum[lane] = v;
    }
    __syncthreads();
    int base = (wp > 0 ? wsum[wp - 1] : 0) + (x - sum);   // exclusive prefix
    g_start[4 * tid + 0] = base;
    g_start[4 * tid + 1] = base + a;
    g_start[4 * tid + 2] = base + a + b;
    g_start[4 * tid + 3] = base + a + b + c;
    if (tid == 1023) g_start[NCELLS] = wsum[31];
}

// ---------------------------------------------------------------------------
// Kernel 3: scatter particle ids into cell-grouped slots (drains g_cnt to 0).
// ---------------------------------------------------------------------------
__global__ __launch_bounds__(256)
void scatter_kernel() {
    const int i = blockIdx.x * 256 + threadIdx.x;
    int c = g_cellid[i];
    int r = atomicSub(&g_cnt[c], 1) - 1;
    g_sortedidx[g_start[c] + r] = i;
}

// ---------------------------------------------------------------------------
// Kernel 4: per-cell ascending sort (determinism) + gather slot-indexed data.
// One thread per cell; cells hold ~1 member (Poisson mean 1).
// ---------------------------------------------------------------------------
__global__ __launch_bounds__(256)
void sortgather_kernel() {
    const int c = blockIdx.x * 256 + threadIdx.x;
    const int s = g_start[c], e = g_start[c + 1];
    for (int a = s + 1; a < e; a++) {
        int v = g_sortedidx[a];
        int b = a - 1;
        while (b >= s && g_sortedidx[b] > v) {
            g_sortedidx[b + 1] = g_sortedidx[b];
            b--;
        }
        g_sortedidx[b + 1] = v;
    }
    for (int u = s; u < e; u++) {
        int j = g_sortedidx[u];
        s_pos4[u] = g_pos4[j];
        s_mask[u] = g_mask[j];
        s_cell[u] = c;
    }
}

// ---------------------------------------------------------------------------
// Heavy path (ordered form: eps masked by column j only).
// ---------------------------------------------------------------------------
__device__ __forceinline__ float pair_e(float r2, float ri, float rj, float mj,
                                        int ig, int jg,
                                        const float* __restrict__ ct) {
    float dr = sqrtf(r2);
    float t  = R_C2 - r2;
    float poly = t * t * (R_C2 + 2.0f * r2 - 3.0f * R_ON2) * CUT_INV_DENOM;
    float cut  = (r2 < R_ON2) ? 1.0f : poly;
    const float4* __restrict__ wi4 = (const float4*)(g_w + ig * NC);
    const float4* __restrict__ ci4 = (const float4*)(ct + ig * NC);
    const float4* __restrict__ wj4 = (const float4*)(g_w + jg * NC);
    const float4* __restrict__ cj4 = (const float4*)(ct + jg * NC);
    float dot = 0.0f;
#pragma unroll
    for (int q = 0; q < 4; q++) {
        float4 wi = wi4[q], ci = ci4[q], wj = wj4[q], cj = cj4[q];
        dot = fmaf(wi.x, cj.x, dot); dot = fmaf(wj.x, ci.x, dot);
        dot = fmaf(wi.y, cj.y, dot); dot = fmaf(wj.y, ci.y, dot);
        dot = fmaf(wi.z, cj.z, dot); dot = fmaf(wj.z, ci.z, dot);
        dot = fmaf(wi.w, cj.w, dot); dot = fmaf(wj.w, ci.w, dot);
    }
    float er  = 0.5f * dot;
    float eps = (__fdividef(5.0f, 1.0f + __expf(-er)) + 0.3f) * mj;
    float u   = 1.0f - __expf(-ALPHA_F * (dr - (ri + rj)));
    return eps * (u * u - 1.0f) * cut;
}

// ---------------------------------------------------------------------------
// Kernel 5: energy. One thread per (sorted slot, (dy,dz) plane): scans one
// contiguous x-strip of <=3 cells (~3 slots). 144 blocks x 256 threads.
// Deterministic: fixed mapping, sorted slots, ascending iteration.
// ---------------------------------------------------------------------------
__global__ __launch_bounds__(256)
void energy_kernel(const float* __restrict__ ct, float* __restrict__ out) {
    __shared__ float red[256];
    __shared__ bool  is_last;

    const int t    = blockIdx.x * 256 + threadIdx.x;  // 0 .. 36863
    const int tid  = threadIdx.x;
    const int slot = t / 9;
    const int r    = t - slot * 9;

    const int   cid = s_cell[slot];
    const float4 pi = s_pos4[slot];

    float acc = 0.0f;

    const int cx  = cid & 15;
    const int cy2 = ((cid >> 4) & 15) + (r % 3) - 1;
    const int cz2 = (cid >> 8) + (r / 3) - 1;

    if (cy2 >= 0 && cy2 < NCELL_DIM && cz2 >= 0 && cz2 < NCELL_DIM) {
        const int xlo  = max(cx - 1, 0);
        const int xhi  = min(cx + 1, NCELL_DIM - 1);
        const int base = (cz2 << 8) | (cy2 << 4);
        const int js   = g_start[base + xlo];
        const int je   = g_start[base + xhi + 1];
        for (int u = js; u < je; u++) {
            if (u == slot) continue;                  // exact self-exclusion
            float4 pj = s_pos4[u];
            float dx = pi.x - pj.x, dy = pi.y - pj.y, dz = pi.z - pj.z;
            float r2 = fmaf(dx, dx, fmaf(dy, dy, dz * dz));
            if (r2 < R_C2) {
                acc += pair_e(r2, pi.w, pj.w, s_mask[u],
                              g_sortedidx[slot], g_sortedidx[u], ct);
            }
        }
    }

    // deterministic block tree-reduce
    red[tid] = acc;
    __syncthreads();
#pragma unroll
    for (int s = 128; s > 0; s >>= 1) {
        if (tid < s) red[tid] += red[tid + s];
        __syncthreads();
    }

    if (tid == 0) {
        g_part[blockIdx.x] = red[0];
        __threadfence();
        unsigned int done = atomicAdd(&g_count, 1u);
        is_last = (done == EBLOCKS - 1);
    }
    __syncthreads();

    if (is_last) {
        red[tid] = (tid < EBLOCKS) ? g_part[tid] : 0.0f;
        __syncthreads();
#pragma unroll
        for (int s = 128; s > 0; s >>= 1) {
            if (tid < s) red[tid] += red[tid + s];
            __syncthreads();
        }
        if (tid == 0) {
            out[0] = 0.5f * red[0];
            g_count = 0;                              // restore for next replay
        }
    }
}

// ---------------------------------------------------------------------------
// Launch. Inputs (metadata order): position (N*3), celltype (N*16),
// epsilon (N*256), radius (N). Output: scalar float.
// ---------------------------------------------------------------------------
extern "C" void kernel_launch(void* const* d_in, const int* in_sizes, int n_in,
                              void* d_out, int out_size) {
    const float* pos = (const float*)d_in[0];
    const float* ct  = (const float*)d_in[1];
    const float* E   = (const float*)d_in[2];
    const float* rad = (const float*)d_in[3];
    float* out = (float*)d_out;

    prep_kernel<<<NPART * NC / 128, 128>>>(pos, ct, E, rad);
    scan_kernel<<<1, 1024>>>();
    scatter_kernel<<<NPART / 256, 256>>>();
    sortgather_kernel<<<NCELLS / 256, 256>>>();
    energy_kernel<<<EBLOCKS, 256>>>(ct, out);
}

// round 8
// speedup vs baseline: 1.0906x; 1.0906x over previous
#include <cuda_runtime.h>
#include <math.h>

#define NPART 4096
#define NC 16

#define R_ON2  (1.7f * 1.7f)       /* 2.89  */
#define R_C2   (4.0f)              /* 2.0^2 */
#define CUT_INV_DENOM (1.0f / ((R_C2 - R_ON2) * (R_C2 - R_ON2) * (R_C2 - R_ON2)))
#define ALPHA_F 2.8f

#define NCELL_DIM 16
#define NCELLS (NCELL_DIM * NCELL_DIM * NCELL_DIM)   /* 4096 */
#define INV_CELLW 0.4f                               /* 1 / 2.5 */

#define EBLOCKS 144                                  /* 4096*9/256 */
#define MAXK 24                                      /* per-strip id cap */

// scratch (no allocations; zero-initialized at load; all counters return to
// zero by end of each launch -> graph replays see identical initial state)
__device__ float  g_w[NPART * NC];    // w_i[d] = 0.5*sum_c ct[c]*(E[c,d]+E[d,c])
__device__ float  g_mask[NPART];      // column mask: sum(ct_j) > 0
__device__ float4 g_pos4[NPART];      // x,y,z,radius
__device__ int    g_cellid[NPART];
__device__ int    g_cnt[NCELLS];      // histogram; scatter drains back to 0
__device__ int    g_start[NCELLS + 1];
__device__ int    g_sortedidx[NPART]; // particle ids grouped by cell (any order)
__device__ float  g_part[EBLOCKS];
__device__ unsigned int g_count;

// ---------------------------------------------------------------------------
// Kernel 1: per-particle contraction w_i = ct_i^T E_sym_i, mask, pos4 pack,
// cell binning. One thread per (particle, dim).
// ---------------------------------------------------------------------------
__global__ __launch_bounds__(128)
void prep_kernel(const float* __restrict__ pos,
                 const float* __restrict__ ct,
                 const float* __restrict__ E,
                 const float* __restrict__ rad) {
    const int t = blockIdx.x * 128 + threadIdx.x;   // 0 .. 65535
    const int i = t >> 4;
    const int d = t & 15;

    const float4* __restrict__ ct4 = (const float4*)(ct + i * NC);
    float4 c0 = ct4[0], c1 = ct4[1], c2 = ct4[2], c3 = ct4[3];
    float sct[16] = {c0.x, c0.y, c0.z, c0.w, c1.x, c1.y, c1.z, c1.w,
                     c2.x, c2.y, c2.z, c2.w, c3.x, c3.y, c3.z, c3.w};

    const float4* __restrict__ Er4 = (const float4*)(E + i * 256 + d * NC);
    float4 r0 = Er4[0], r1 = Er4[1], r2 = Er4[2], r3 = Er4[3];
    float er[16] = {r0.x, r0.y, r0.z, r0.w, r1.x, r1.y, r1.z, r1.w,
                    r2.x, r2.y, r2.z, r2.w, r3.x, r3.y, r3.z, r3.w};

    const float* __restrict__ Ec = E + i * 256 + d;
    float w = 0.0f;
#pragma unroll
    for (int c = 0; c < 16; c++) {
        w = fmaf(sct[c], er[c] + __ldg(Ec + c * 16), w);
    }
    g_w[t] = 0.5f * w;

    if (d == 0) {
        float s = 0.0f;
#pragma unroll
        for (int c = 0; c < 16; c++) s += sct[c];
        g_mask[i] = (s > 0.0f) ? 1.0f : 0.0f;
        float px = pos[3 * i], py = pos[3 * i + 1], pz = pos[3 * i + 2];
        g_pos4[i] = make_float4(px, py, pz, rad[i]);
        int cx = min((int)(px * INV_CELLW), NCELL_DIM - 1);
        int cy = min((int)(py * INV_CELLW), NCELL_DIM - 1);
        int cz = min((int)(pz * INV_CELLW), NCELL_DIM - 1);
        int cell = (cz << 8) | (cy << 4) | cx;
        g_cellid[i] = cell;
        atomicAdd(&g_cnt[cell], 1);
    }
}

// ---------------------------------------------------------------------------
// Kernel 2: exclusive scan of 4096 cell counts. One block, 1024 threads,
// shfl-based (2 barriers total).
// ---------------------------------------------------------------------------
__global__ __launch_bounds__(1024)
void scan_kernel() {
    __shared__ int wsum[32];
    const int tid = threadIdx.x, lane = tid & 31, wp = tid >> 5;
    int a = g_cnt[4 * tid + 0];
    int b = g_cnt[4 * tid + 1];
    int c = g_cnt[4 * tid + 2];
    int d = g_cnt[4 * tid + 3];
    int sum = a + b + c + d;
    int x = sum;
#pragma unroll
    for (int off = 1; off < 32; off <<= 1) {
        int y = __shfl_up_sync(0xffffffffu, x, off);
        if (lane >= off) x += y;
    }
    if (lane == 31) wsum[wp] = x;
    __syncthreads();
    if (wp == 0) {
        int v = wsum[lane];
#pragma unroll
        for (int off = 1; off < 32; off <<= 1) {
            int y = __shfl_up_sync(0xffffffffu, v, off);
            if (lane >= off) v += y;
        }
        wsum[lane] = v;
    }
    __syncthreads();
    int base = (wp > 0 ? wsum[wp - 1] : 0) + (x - sum);   // exclusive prefix
    g_start[4 * tid + 0] = base;
    g_start[4 * tid + 1] = base + a;
    g_start[4 * tid + 2] = base + a + b;
    g_start[4 * tid + 3] = base + a + b + c;
    if (tid == 1023) g_start[NCELLS] = wsum[31];
}

// ---------------------------------------------------------------------------
// Kernel 3: scatter particle ids into cell-grouped slots (drains g_cnt to 0).
// Within-cell order is arbitrary; the energy kernel sorts ids in registers.
// ---------------------------------------------------------------------------
__global__ __launch_bounds__(256)
void scatter_kernel() {
    const int i = blockIdx.x * 256 + threadIdx.x;
    int c = g_cellid[i];
    int r = atomicSub(&g_cnt[c], 1) - 1;
    g_sortedidx[g_start[c] + r] = i;
}

// ---------------------------------------------------------------------------
// Heavy path (ordered form: eps masked by column j only).
// ---------------------------------------------------------------------------
__device__ __forceinline__ float pair_e(float r2, float ri, float rj, float mj,
                                        int ig, int jg,
                                        const float* __restrict__ ct) {
    float dr = sqrtf(r2);
    float t  = R_C2 - r2;
    float poly = t * t * (R_C2 + 2.0f * r2 - 3.0f * R_ON2) * CUT_INV_DENOM;
    float cut  = (r2 < R_ON2) ? 1.0f : poly;
    const float4* __restrict__ wi4 = (const float4*)(g_w + ig * NC);
    const float4* __restrict__ ci4 = (const float4*)(ct + ig * NC);
    const float4* __restrict__ wj4 = (const float4*)(g_w + jg * NC);
    const float4* __restrict__ cj4 = (const float4*)(ct + jg * NC);
    float dot = 0.0f;
#pragma unroll
    for (int q = 0; q < 4; q++) {
        float4 wi = wi4[q], ci = ci4[q], wj = wj4[q], cj = cj4[q];
        dot = fmaf(wi.x, cj.x, dot); dot = fmaf(wj.x, ci.x, dot);
        dot = fmaf(wi.y, cj.y, dot); dot = fmaf(wj.y, ci.y, dot);
        dot = fmaf(wi.z, cj.z, dot); dot = fmaf(wj.z, ci.z, dot);
        dot = fmaf(wi.w, cj.w, dot); dot = fmaf(wj.w, ci.w, dot);
    }
    float er  = 0.5f * dot;
    float eps = (__fdividef(5.0f, 1.0f + __expf(-er)) + 0.3f) * mj;
    float u   = 1.0f - __expf(-ALPHA_F * (dr - (ri + rj)));
    return eps * (u * u - 1.0f) * cut;
}

// ---------------------------------------------------------------------------
// Kernel 4: energy. One thread per (particle, (dy,dz) plane): scans one
// contiguous x-strip of <=3 cells. Ids loaded in parallel, sorted ascending
// in registers (determinism), then evaluated. Fused final reduction.
// ---------------------------------------------------------------------------
__global__ __launch_bounds__(256)
void energy_kernel(const float* __restrict__ ct, float* __restrict__ out) {
    __shared__ float red[256];
    __shared__ bool  is_last;

    const int t   = blockIdx.x * 256 + threadIdx.x;  // 0 .. 36863
    const int tid = threadIdx.x;
    const int i   = t / 9;
    const int r   = t - i * 9;

    const int    cid = g_cellid[i];
    const float4 pi  = g_pos4[i];

    float acc = 0.0f;

    const int cx  = cid & 15;
    const int cy2 = ((cid >> 4) & 15) + (r % 3) - 1;
    const int cz2 = (cid >> 8) + (r / 3) - 1;

    if (cy2 >= 0 && cy2 < NCELL_DIM && cz2 >= 0 && cz2 < NCELL_DIM) {
        const int xlo  = max(cx - 1, 0);
        const int xhi  = min(cx + 1, NCELL_DIM - 1);
        const int base = (cz2 << 8) | (cy2 << 4);
        const int js   = g_start[base + xlo];
        const int je   = g_start[base + xhi + 1];
        const int k    = je - js;

        if (k <= MAXK) {
            int ids[MAXK];
            for (int u = 0; u < k; u++) ids[u] = g_sortedidx[js + u];
            // ascending insertion sort (ALU only; k ~ 3)
            for (int a = 1; a < k; a++) {
                int v = ids[a];
                int b = a - 1;
                while (b >= 0 && ids[b] > v) { ids[b + 1] = ids[b]; b--; }
                ids[b + 1] = v;
            }
            for (int u = 0; u < k; u++) {
                int j = ids[u];
                if (j == i) continue;
                float4 pj = g_pos4[j];
                float dx = pi.x - pj.x, dy = pi.y - pj.y, dz = pi.z - pj.z;
                float r2 = fmaf(dx, dx, fmaf(dy, dy, dz * dz));
                if (r2 < R_C2) {
                    acc += pair_e(r2, pi.w, pj.w, g_mask[j], i, j, ct);
                }
            }
        } else {
            // never expected (Poisson tail); correct ascending fallback
            int last = -1;
            for (int m = 0; m < k; m++) {
                int best = 1 << 30;
                for (int u = js; u < je; u++) {
                    int j = g_sortedidx[u];
                    if (j > last && j < best) best = j;
                }
                last = best;
                if (best == i) continue;
                float4 pj = g_pos4[best];
                float dx = pi.x - pj.x, dy = pi.y - pj.y, dz = pi.z - pj.z;
                float r2 = fmaf(dx, dx, fmaf(dy, dy, dz * dz));
                if (r2 < R_C2) {
                    acc += pair_e(r2, pi.w, pj.w, g_mask[best], i, best, ct);
                }
            }
        }
    }

    // deterministic block tree-reduce
    red[tid] = acc;
    __syncthreads();
#pragma unroll
    for (int s = 128; s > 0; s >>= 1) {
        if (tid < s) red[tid] += red[tid + s];
        __syncthreads();
    }

    if (tid == 0) {
        g_part[blockIdx.x] = red[0];
        __threadfence();
        unsigned int done = atomicAdd(&g_count, 1u);
        is_last = (done == EBLOCKS - 1);
    }
    __syncthreads();

    if (is_last) {
        red[tid] = (tid < EBLOCKS) ? g_part[tid] : 0.0f;
        __syncthreads();
#pragma unroll
        for (int s = 128; s > 0; s >>= 1) {
            if (tid < s) red[tid] += red[tid + s];
            __syncthreads();
        }
        if (tid == 0) {
            out[0] = 0.5f * red[0];
            g_count = 0;                              // restore for next replay
        }
    }
}

// ---------------------------------------------------------------------------
// Launch. Inputs (metadata order): position (N*3), celltype (N*16),
// epsilon (N*256), radius (N). Output: scalar float.
// ---------------------------------------------------------------------------
extern "C" void kernel_launch(void* const* d_in, const int* in_sizes, int n_in,
                              void* d_out, int out_size) {
    const float* pos = (const float*)d_in[0];
    const float* ct  = (const float*)d_in[1];
    const float* E   = (const float*)d_in[2];
    const float* rad = (const float*)d_in[3];
    float* out = (float*)d_out;

    prep_kernel<<<NPART * NC / 128, 128>>>(pos, ct, E, rad);
    scan_kernel<<<1, 1024>>>();
    scatter_kernel<<<NPART / 256, 256>>>();
    energy_kernel<<<EBLOCKS, 256>>>(ct, out);
}

// round 9
// speedup vs baseline: 1.1875x; 1.0889x over previous
#include <cuda_runtime.h>
#include <math.h>

#define NPART 4096
#define NC 16

#define R_ON2  (1.7f * 1.7f)       /* 2.89  */
#define R_C2   (4.0f)              /* 2.0^2 */
#define CUT_INV_DENOM (1.0f / ((R_C2 - R_ON2) * (R_C2 - R_ON2) * (R_C2 - R_ON2)))
#define ALPHA_F 2.8f

#define NCELL_DIM 16
#define NCELLS (NCELL_DIM * NCELL_DIM * NCELL_DIM)   /* 4096 */
#define INV_CELLW 0.4f                               /* 1 / 2.5 */

#define EBLOCKS 432                                  /* 4096*27/256 */
#define MAXK 6                                       /* register sort width */

// scratch (no allocations; zero-initialized at load; all counters return to
// zero by end of each launch -> graph replays see identical initial state)
__device__ float  g_w[NPART * NC];    // w_i[d] = 0.5*sum_c ct[c]*(E[c,d]+E[d,c])
__device__ float  g_mask[NPART];      // column mask: sum(ct_j) > 0
__device__ float4 g_pos4[NPART];      // x,y,z,radius
__device__ int    g_cellid[NPART];
__device__ int    g_cnt[NCELLS];      // histogram; scatter drains back to 0
__device__ int    g_start[NCELLS + 1];
__device__ int    g_sortedidx[NPART]; // particle ids grouped by cell (any order)
__device__ float  g_part[EBLOCKS];
__device__ unsigned int g_count;

// ---------------------------------------------------------------------------
// Kernel 1: per-particle contraction w_i = ct_i^T E_sym_i, mask, pos4 pack,
// cell binning. One thread per (particle, dim).
// ---------------------------------------------------------------------------
__global__ __launch_bounds__(128)
void prep_kernel(const float* __restrict__ pos,
                 const float* __restrict__ ct,
                 const float* __restrict__ E,
                 const float* __restrict__ rad) {
    const int t = blockIdx.x * 128 + threadIdx.x;   // 0 .. 65535
    const int i = t >> 4;
    const int d = t & 15;

    const float4* __restrict__ ct4 = (const float4*)(ct + i * NC);
    float4 c0 = ct4[0], c1 = ct4[1], c2 = ct4[2], c3 = ct4[3];
    float sct[16] = {c0.x, c0.y, c0.z, c0.w, c1.x, c1.y, c1.z, c1.w,
                     c2.x, c2.y, c2.z, c2.w, c3.x, c3.y, c3.z, c3.w};

    const float4* __restrict__ Er4 = (const float4*)(E + i * 256 + d * NC);
    float4 r0 = Er4[0], r1 = Er4[1], r2 = Er4[2], r3 = Er4[3];
    float er[16] = {r0.x, r0.y, r0.z, r0.w, r1.x, r1.y, r1.z, r1.w,
                    r2.x, r2.y, r2.z, r2.w, r3.x, r3.y, r3.z, r3.w};

    const float* __restrict__ Ec = E + i * 256 + d;
    float w = 0.0f;
#pragma unroll
    for (int c = 0; c < 16; c++) {
        w = fmaf(sct[c], er[c] + __ldg(Ec + c * 16), w);
    }
    g_w[t] = 0.5f * w;

    if (d == 0) {
        float s = 0.0f;
#pragma unroll
        for (int c = 0; c < 16; c++) s += sct[c];
        g_mask[i] = (s > 0.0f) ? 1.0f : 0.0f;
        float px = pos[3 * i], py = pos[3 * i + 1], pz = pos[3 * i + 2];
        g_pos4[i] = make_float4(px, py, pz, rad[i]);
        int cx = min((int)(px * INV_CELLW), NCELL_DIM - 1);
        int cy = min((int)(py * INV_CELLW), NCELL_DIM - 1);
        int cz = min((int)(pz * INV_CELLW), NCELL_DIM - 1);
        int cell = (cz << 8) | (cy << 4) | cx;
        g_cellid[i] = cell;
        atomicAdd(&g_cnt[cell], 1);
    }
}

// ---------------------------------------------------------------------------
// Kernel 2: exclusive scan of 4096 cell counts. One block, 1024 threads,
// shfl-based (2 barriers total).
// ---------------------------------------------------------------------------
__global__ __launch_bounds__(1024)
void scan_kernel() {
    __shared__ int wsum[32];
    const int tid = threadIdx.x, lane = tid & 31, wp = tid >> 5;
    int a = g_cnt[4 * tid + 0];
    int b = g_cnt[4 * tid + 1];
    int c = g_cnt[4 * tid + 2];
    int d = g_cnt[4 * tid + 3];
    int sum = a + b + c + d;
    int x = sum;
#pragma unroll
    for (int off = 1; off < 32; off <<= 1) {
        int y = __shfl_up_sync(0xffffffffu, x, off);
        if (lane >= off) x += y;
    }
    if (lane == 31) wsum[wp] = x;
    __syncthreads();
    if (wp == 0) {
        int v = wsum[lane];
#pragma unroll
        for (int off = 1; off < 32; off <<= 1) {
            int y = __shfl_up_sync(0xffffffffu, v, off);
            if (lane >= off) v += y;
        }
        wsum[lane] = v;
    }
    __syncthreads();
    int base = (wp > 0 ? wsum[wp - 1] : 0) + (x - sum);   // exclusive prefix
    g_start[4 * tid + 0] = base;
    g_start[4 * tid + 1] = base + a;
    g_start[4 * tid + 2] = base + a + b;
    g_start[4 * tid + 3] = base + a + b + c;
    if (tid == 1023) g_start[NCELLS] = wsum[31];
}

// ---------------------------------------------------------------------------
// Kernel 3: scatter particle ids into cell-grouped slots (drains g_cnt to 0).
// Within-cell order is arbitrary; the energy kernel sorts ids in registers.
// ---------------------------------------------------------------------------
__global__ __launch_bounds__(256)
void scatter_kernel() {
    const int i = blockIdx.x * 256 + threadIdx.x;
    int c = g_cellid[i];
    int r = atomicSub(&g_cnt[c], 1) - 1;
    g_sortedidx[g_start[c] + r] = i;
}

// ---------------------------------------------------------------------------
// Heavy path (ordered form: eps masked by column j only). Rare -> noinline
// keeps one code copy; ABI call cost is noise at ~17K total calls.
// ---------------------------------------------------------------------------
__device__ __noinline__ float pair_e(float r2, float ri, float rj, float mj,
                                     int ig, int jg,
                                     const float* __restrict__ ct) {
    float dr = sqrtf(r2);
    float t  = R_C2 - r2;
    float poly = t * t * (R_C2 + 2.0f * r2 - 3.0f * R_ON2) * CUT_INV_DENOM;
    float cut  = (r2 < R_ON2) ? 1.0f : poly;
    const float4* __restrict__ wi4 = (const float4*)(g_w + ig * NC);
    const float4* __restrict__ ci4 = (const float4*)(ct + ig * NC);
    const float4* __restrict__ wj4 = (const float4*)(g_w + jg * NC);
    const float4* __restrict__ cj4 = (const float4*)(ct + jg * NC);
    float dot = 0.0f;
#pragma unroll
    for (int q = 0; q < 4; q++) {
        float4 wi = wi4[q], ci = ci4[q], wj = wj4[q], cj = cj4[q];
        dot = fmaf(wi.x, cj.x, dot); dot = fmaf(wj.x, ci.x, dot);
        dot = fmaf(wi.y, cj.y, dot); dot = fmaf(wj.y, ci.y, dot);
        dot = fmaf(wi.z, cj.z, dot); dot = fmaf(wj.z, ci.z, dot);
        dot = fmaf(wi.w, cj.w, dot); dot = fmaf(wj.w, ci.w, dot);
    }
    float er  = 0.5f * dot;
    float eps = (__fdividef(5.0f, 1.0f + __expf(-er)) + 0.3f) * mj;
    float u   = 1.0f - __expf(-ALPHA_F * (dr - (ri + rj)));
    return eps * (u * u - 1.0f) * cut;
}

// ---------------------------------------------------------------------------
// Kernel 4: energy. One thread per (particle, neighbor cell): 4096*27 threads,
// 432 blocks. Cell members (mean 1) sorted ascending via a fixed 6-wide
// register bubble network (no local memory); deterministic min-selection
// fallback for the ~1-in-12000 cells with >6 members. Fused final reduction.
// ---------------------------------------------------------------------------
__global__ __launch_bounds__(256)
void energy_kernel(const float* __restrict__ ct, float* __restrict__ out) {
    __shared__ float red[256];
    __shared__ bool  is_last;

    const int t   = blockIdx.x * 256 + threadIdx.x;  // 0 .. 110591
    const int tid = threadIdx.x;
    const int i   = t / 27;
    const int r   = t - i * 27;

    const float4 pi = g_pos4[i];

    // recompute home cell from position (skips one dependent load round)
    const int cx = min((int)(pi.x * INV_CELLW), NCELL_DIM - 1) + (r % 3) - 1;
    const int cy = min((int)(pi.y * INV_CELLW), NCELL_DIM - 1) + ((r / 3) % 3) - 1;
    const int cz = min((int)(pi.z * INV_CELLW), NCELL_DIM - 1) + (r / 9) - 1;

    float acc = 0.0f;

    if (cx >= 0 && cx < NCELL_DIM && cy >= 0 && cy < NCELL_DIM &&
        cz >= 0 && cz < NCELL_DIM) {
        const int nc = (cz << 8) | (cy << 4) | cx;
        const int js = g_start[nc];
        const int je = g_start[nc + 1];
        const int k  = je - js;

        if (k > 0) {
            if (k <= MAXK) {
                // predicated parallel loads into fixed registers
                int ids[MAXK];
#pragma unroll
                for (int u = 0; u < MAXK; u++)
                    ids[u] = (u < k) ? __ldg(&g_sortedidx[js + u]) : 0x7fffffff;
                // fixed bubble network: constant indices -> pure registers
#pragma unroll
                for (int a = 0; a < MAXK - 1; a++) {
#pragma unroll
                    for (int b = 0; b < MAXK - 1 - a; b++) {
                        int lo = min(ids[b], ids[b + 1]);
                        int hi = max(ids[b], ids[b + 1]);
                        ids[b] = lo; ids[b + 1] = hi;
                    }
                }
#pragma unroll
                for (int u = 0; u < MAXK; u++) {
                    int j = ids[u];
                    if (j < NPART && j != i) {
                        float4 pj = g_pos4[j];
                        float dx = pi.x - pj.x, dy = pi.y - pj.y, dz = pi.z - pj.z;
                        float r2 = fmaf(dx, dx, fmaf(dy, dy, dz * dz));
                        if (r2 < R_C2)
                            acc += pair_e(r2, pi.w, pj.w, g_mask[j], i, j, ct);
                    }
                }
            } else {
                // rare: deterministic ascending min-selection
                int last = -1;
                for (int m = 0; m < k; m++) {
                    int best = 0x7fffffff;
                    for (int u = js; u < je; u++) {
                        int j = g_sortedidx[u];
                        if (j > last && j < best) best = j;
                    }
                    last = best;
                    if (best == i) continue;
                    float4 pj = g_pos4[best];
                    float dx = pi.x - pj.x, dy = pi.y - pj.y, dz = pi.z - pj.z;
                    float r2 = fmaf(dx, dx, fmaf(dy, dy, dz * dz));
                    if (r2 < R_C2)
                        acc += pair_e(r2, pi.w, pj.w, g_mask[best], i, best, ct);
                }
            }
        }
    }

    // deterministic block tree-reduce
    red[tid] = acc;
    __syncthreads();
#pragma unroll
    for (int s = 128; s > 0; s >>= 1) {
        if (tid < s) red[tid] += red[tid + s];
        __syncthreads();
    }

    if (tid == 0) {
        g_part[blockIdx.x] = red[0];
        __threadfence();
        unsigned int done = atomicAdd(&g_count, 1u);
        is_last = (done == EBLOCKS - 1);
    }
    __syncthreads();

    if (is_last) {
        float v = g_part[tid];
        if (tid < EBLOCKS - 256) v += g_part[tid + 256];
        red[tid] = v;
        __syncthreads();
#pragma unroll
        for (int s = 128; s > 0; s >>= 1) {
            if (tid < s) red[tid] += red[tid + s];
            __syncthreads();
        }
        if (tid == 0) {
            out[0] = 0.5f * red[0];
            g_count = 0;                              // restore for next replay
        }
    }
}

// ---------------------------------------------------------------------------
// Launch. Inputs (metadata order): position (N*3), celltype (N*16),
// epsilon (N*256), radius (N). Output: scalar float.
// ---------------------------------------------------------------------------
extern "C" void kernel_launch(void* const* d_in, const int* in_sizes, int n_in,
                              void* d_out, int out_size) {
    const float* pos = (const float*)d_in[0];
    const float* ct  = (const float*)d_in[1];
    const float* E   = (const float*)d_in[2];
    const float* rad = (const float*)d_in[3];
    float* out = (float*)d_out;

    prep_kernel<<<NPART * NC / 128, 128>>>(pos, ct, E, rad);
    scan_kernel<<<1, 1024>>>();
    scatter_kernel<<<NPART / 256, 256>>>();
    energy_kernel<<<EBLOCKS, 256>>>(ct, out);
}

// round 10
// speedup vs baseline: 1.5981x; 1.3458x over previous
#include <cuda_runtime.h>
#include <math.h>

#define NPART 4096
#define NC 16

#define R_ON2  (1.7f * 1.7f)       /* 2.89  */
#define R_C2   (4.0f)              /* 2.0^2 */
#define CUT_INV_DENOM (1.0f / ((R_C2 - R_ON2) * (R_C2 - R_ON2) * (R_C2 - R_ON2)))
#define ALPHA_F 2.8f

#define NCELL_DIM 16
#define NCELLS (NCELL_DIM * NCELL_DIM * NCELL_DIM)   /* 4096 */
#define INV_CELLW 0.4f                               /* 1 / 2.5 */

#define SLOTS 8                                      /* direct-map width */
#define EBLOCKS 864                                  /* 4096*27/128 */

// scratch (no allocations; zero-initialized at load; counters reset by the
// last energy block -> graph replays see identical initial state)
__device__ float  g_w[NPART * NC];    // w_i[d] = 0.5*sum_c ct[c]*(E[c,d]+E[d,c])
__device__ float  g_mask[NPART];      // column mask: sum(ct_j) > 0
__device__ float4 g_pos4[NPART];      // x,y,z,radius
__device__ int    g_cellid[NPART];
__device__ int    g_ccnt[NCELLS];     // per-cell member count
__device__ int    g_slots[NCELLS * SLOTS];  // direct cell->particle map
__device__ int2   g_ovf[NPART];       // overflow (cell,id); ~never used
__device__ unsigned int g_nov;        // overflow count
__device__ float  g_part[EBLOCKS];
__device__ unsigned int g_count;      // last-block counter

// ---------------------------------------------------------------------------
// Kernel 1: per-particle contraction w_i = ct_i^T E_sym_i, mask, pos4 pack,
// and direct-mapped cell binning. One thread per (particle, dim).
// ---------------------------------------------------------------------------
__global__ __launch_bounds__(128)
void prep_kernel(const float* __restrict__ pos,
                 const float* __restrict__ ct,
                 const float* __restrict__ E,
                 const float* __restrict__ rad) {
    const int t = blockIdx.x * 128 + threadIdx.x;   // 0 .. 65535
    const int i = t >> 4;
    const int d = t & 15;

    const float4* __restrict__ ct4 = (const float4*)(ct + i * NC);
    float4 c0 = ct4[0], c1 = ct4[1], c2 = ct4[2], c3 = ct4[3];
    float sct[16] = {c0.x, c0.y, c0.z, c0.w, c1.x, c1.y, c1.z, c1.w,
                     c2.x, c2.y, c2.z, c2.w, c3.x, c3.y, c3.z, c3.w};

    const float4* __restrict__ Er4 = (const float4*)(E + i * 256 + d * NC);
    float4 r0 = Er4[0], r1 = Er4[1], r2 = Er4[2], r3 = Er4[3];
    float er[16] = {r0.x, r0.y, r0.z, r0.w, r1.x, r1.y, r1.z, r1.w,
                    r2.x, r2.y, r2.z, r2.w, r3.x, r3.y, r3.z, r3.w};

    const float* __restrict__ Ec = E + i * 256 + d;
    float w = 0.0f;
#pragma unroll
    for (int c = 0; c < 16; c++) {
        w = fmaf(sct[c], er[c] + __ldg(Ec + c * 16), w);
    }
    g_w[t] = 0.5f * w;

    if (d == 0) {
        float s = 0.0f;
#pragma unroll
        for (int c = 0; c < 16; c++) s += sct[c];
        g_mask[i] = (s > 0.0f) ? 1.0f : 0.0f;
        float px = pos[3 * i], py = pos[3 * i + 1], pz = pos[3 * i + 2];
        g_pos4[i] = make_float4(px, py, pz, rad[i]);
        int cx = min((int)(px * INV_CELLW), NCELL_DIM - 1);
        int cy = min((int)(py * INV_CELLW), NCELL_DIM - 1);
        int cz = min((int)(pz * INV_CELLW), NCELL_DIM - 1);
        int cell = (cz << 8) | (cy << 4) | cx;
        g_cellid[i] = cell;
        int r = atomicAdd(&g_ccnt[cell], 1);
        if (r < SLOTS) {
            g_slots[cell * SLOTS + r] = i;
        } else {
            unsigned o = atomicAdd(&g_nov, 1u);
            g_ovf[o] = make_int2(cell, i);
        }
    }
}

// ---------------------------------------------------------------------------
// Heavy path (ordered form: eps masked by column j only). Rare -> noinline.
// ---------------------------------------------------------------------------
__device__ __noinline__ float pair_e(float r2, float ri, float rj, float mj,
                                     int ig, int jg,
                                     const float* __restrict__ ct) {
    float dr = sqrtf(r2);
    float t  = R_C2 - r2;
    float poly = t * t * (R_C2 + 2.0f * r2 - 3.0f * R_ON2) * CUT_INV_DENOM;
    float cut  = (r2 < R_ON2) ? 1.0f : poly;
    const float4* __restrict__ wi4 = (const float4*)(g_w + ig * NC);
    const float4* __restrict__ ci4 = (const float4*)(ct + ig * NC);
    const float4* __restrict__ wj4 = (const float4*)(g_w + jg * NC);
    const float4* __restrict__ cj4 = (const float4*)(ct + jg * NC);
    float dot = 0.0f;
#pragma unroll
    for (int q = 0; q < 4; q++) {
        float4 wi = wi4[q], ci = ci4[q], wj = wj4[q], cj = cj4[q];
        dot = fmaf(wi.x, cj.x, dot); dot = fmaf(wj.x, ci.x, dot);
        dot = fmaf(wi.y, cj.y, dot); dot = fmaf(wj.y, ci.y, dot);
        dot = fmaf(wi.z, cj.z, dot); dot = fmaf(wj.z, ci.z, dot);
        dot = fmaf(wi.w, cj.w, dot); dot = fmaf(wj.w, ci.w, dot);
    }
    float er  = 0.5f * dot;
    float eps = (__fdividef(5.0f, 1.0f + __expf(-er)) + 0.3f) * mj;
    float u   = 1.0f - __expf(-ALPHA_F * (dr - (ri + rj)));
    return eps * (u * u - 1.0f) * cut;
}

#define CE(a, b) { int lo = min(ids[a], ids[b]); int hi = max(ids[a], ids[b]); \
                   ids[a] = lo; ids[b] = hi; }

// ---------------------------------------------------------------------------
// Kernel 2: energy. One thread per (particle, neighbor cell): 4096*27 =
// 110592 threads, 864 blocks x 128. Chain: (cellid || pos4) -> (cnt || two
// LDG.128 slot loads) -> pos4[j]. Ids sorted ascending by a Batcher-8
// network in registers (determinism). Fused final reduction + counter reset.
// ---------------------------------------------------------------------------
__global__ __launch_bounds__(128)
void energy_kernel(const float* __restrict__ ct, float* __restrict__ out) {
    __shared__ float red[128];
    __shared__ bool  is_last;

    const int t   = blockIdx.x * 128 + threadIdx.x;  // 0 .. 110591
    const int tid = threadIdx.x;
    const int i   = t / 27;
    const int r   = t - i * 27;

    const int    cid = g_cellid[i];   // issued in parallel with pi
    const float4 pi  = g_pos4[i];

    const int cx = (cid & 15)        + (r % 3) - 1;
    const int cy = ((cid >> 4) & 15) + ((r / 3) % 3) - 1;
    const int cz = (cid >> 8)        + (r / 9) - 1;

    float acc = 0.0f;

    if (cx >= 0 && cx < NCELL_DIM && cy >= 0 && cy < NCELL_DIM &&
        cz >= 0 && cz < NCELL_DIM) {
        const int nc = (cz << 8) | (cy << 4) | cx;
        const int k  = g_ccnt[nc];                         // LDG
        const int4 s0 = ((const int4*)g_slots)[nc * 2];    // LDG.128 (parallel)
        const int4 s1 = ((const int4*)g_slots)[nc * 2 + 1];

        if (k > 0) {
            int ids[8] = {s0.x, s0.y, s0.z, s0.w, s1.x, s1.y, s1.z, s1.w};
#pragma unroll
            for (int u = 0; u < 8; u++)
                if (u >= k) ids[u] = 0x7fffffff;           // sentinel pad
            // Batcher odd-even 8-sort (19 compare-exchanges, registers only)
            CE(0,1) CE(2,3) CE(4,5) CE(6,7)
            CE(0,2) CE(1,3) CE(4,6) CE(5,7)
            CE(1,2) CE(5,6)
            CE(0,4) CE(1,5) CE(2,6) CE(3,7)
            CE(2,4) CE(3,5)
            CE(1,2) CE(3,4) CE(5,6)
#pragma unroll
            for (int u = 0; u < 8; u++) {
                int j = ids[u];
                if (j < NPART && j != i) {
                    float4 pj = g_pos4[j];
                    float dx = pi.x - pj.x, dy = pi.y - pj.y, dz = pi.z - pj.z;
                    float r2 = fmaf(dx, dx, fmaf(dy, dy, dz * dz));
                    if (r2 < R_C2)
                        acc += pair_e(r2, pi.w, pj.w, g_mask[j], i, j, ct);
                }
            }
            if (k > SLOTS) {
                // correct (never-expected) overflow path: members beyond the
                // 8 slots live in g_ovf; process ascending by id
                unsigned nov = g_nov;
                int last = -1;
                for (int m = 0; m < k - SLOTS; m++) {
                    int best = 0x7fffffff;
                    for (unsigned u = 0; u < nov; u++) {
                        int2 e = g_ovf[u];
                        if (e.x == nc && e.y > last && e.y < best) best = e.y;
                    }
                    if (best == 0x7fffffff) break;
                    last = best;
                    if (best == i) continue;
                    float4 pj = g_pos4[best];
                    float dx = pi.x - pj.x, dy = pi.y - pj.y, dz = pi.z - pj.z;
                    float r2 = fmaf(dx, dx, fmaf(dy, dy, dz * dz));
                    if (r2 < R_C2)
                        acc += pair_e(r2, pi.w, pj.w, g_mask[best], i, best, ct);
                }
            }
        }
    }

    // deterministic block tree-reduce (128 threads)
    red[tid] = acc;
    __syncthreads();
#pragma unroll
    for (int s = 64; s > 0; s >>= 1) {
        if (tid < s) red[tid] += red[tid + s];
        __syncthreads();
    }

    if (tid == 0) {
        g_part[blockIdx.x] = red[0];
        __threadfence();
        unsigned int done = atomicAdd(&g_count, 1u);
        is_last = (done == EBLOCKS - 1);
    }
    __syncthreads();

    if (is_last) {
        // deterministic final reduction of 864 partials (fixed order)
        float v = 0.0f;
#pragma unroll
        for (int q = 0; q < 7; q++) {
            int idx = tid + q * 128;
            if (idx < EBLOCKS) v += g_part[idx];
        }
        red[tid] = v;
        __syncthreads();
#pragma unroll
        for (int s = 64; s > 0; s >>= 1) {
            if (tid < s) red[tid] += red[tid + s];
            __syncthreads();
        }
        if (tid == 0) {
            out[0] = 0.5f * red[0];
            g_count = 0;
            g_nov   = 0;
        }
        // reset per-cell counts for the next graph replay
        for (int c = tid; c < NCELLS; c += 128) g_ccnt[c] = 0;
    }
}

// ---------------------------------------------------------------------------
// Launch. Inputs (metadata order): position (N*3), celltype (N*16),
// epsilon (N*256), radius (N). Output: scalar float.
// ---------------------------------------------------------------------------
extern "C" void kernel_launch(void* const* d_in, const int* in_sizes, int n_in,
                              void* d_out, int out_size) {
    const float* pos = (const float*)d_in[0];
    const float* ct  = (const float*)d_in[1];
    const float* E   = (const float*)d_in[2];
    const float* rad = (const float*)d_in[3];
    float* out = (float*)d_out;

    prep_kernel<<<NPART * NC / 128, 128>>>(pos, ct, E, rad);
    energy_kernel<<<EBLOCKS, 128>>>(ct, out);
}

// round 11
// speedup vs baseline: 1.7962x; 1.1239x over previous
#include <cuda_runtime.h>
#include <math.h>

#define NPART 4096
#define NC 16

#define R_ON2  (1.7f * 1.7f)       /* 2.89  */
#define R_C2   (4.0f)              /* 2.0^2 */
#define CUT_INV_DENOM (1.0f / ((R_C2 - R_ON2) * (R_C2 - R_ON2) * (R_C2 - R_ON2)))
#define ALPHA_F 2.8f

#define NCELL_DIM 16
#define NCELLS (NCELL_DIM * NCELL_DIM * NCELL_DIM)   /* 4096 */
#define INV_CELLW 0.4f                               /* 1 / 2.5 */

#define SLOTS 8                                      /* direct-map width */
#define EBLOCKS 864                                  /* 4096*27/128 */

// scratch (no allocations; zero-initialized at load; counters reset by the
// last energy block -> graph replays see identical initial state)
__device__ float  g_w[NPART * NC];    // w_i[d] = 0.5*sum_c ct[c]*(E[c,d]+E[d,c])
__device__ float  g_mask[NPART];      // column mask: sum(ct_j) > 0
__device__ float4 g_pos4[NPART];      // x,y,z,radius
__device__ int    g_cellid[NPART];
__device__ int    g_ccnt[NCELLS];     // per-cell member count
__device__ int    g_slots[NCELLS * SLOTS];  // direct cell->particle map
__device__ int2   g_ovf[NPART];       // overflow (cell,id); ~never used
__device__ unsigned int g_nov;        // overflow count
__device__ float  g_part[EBLOCKS];
__device__ unsigned int g_count;      // last-block counter

// ---------------------------------------------------------------------------
// Kernel 1: per-particle contraction w_i = ct_i^T E_sym_i, mask, pos4 pack,
// and direct-mapped cell binning. One thread per (particle, dim).
// ---------------------------------------------------------------------------
__global__ __launch_bounds__(128)
void prep_kernel(const float* __restrict__ pos,
                 const float* __restrict__ ct,
                 const float* __restrict__ E,
                 const float* __restrict__ rad) {
    const int t = blockIdx.x * 128 + threadIdx.x;   // 0 .. 65535
    const int i = t >> 4;
    const int d = t & 15;

    const float4* __restrict__ ct4 = (const float4*)(ct + i * NC);
    float4 c0 = ct4[0], c1 = ct4[1], c2 = ct4[2], c3 = ct4[3];
    float sct[16] = {c0.x, c0.y, c0.z, c0.w, c1.x, c1.y, c1.z, c1.w,
                     c2.x, c2.y, c2.z, c2.w, c3.x, c3.y, c3.z, c3.w};

    const float4* __restrict__ Er4 = (const float4*)(E + i * 256 + d * NC);
    float4 r0 = Er4[0], r1 = Er4[1], r2 = Er4[2], r3 = Er4[3];
    float er[16] = {r0.x, r0.y, r0.z, r0.w, r1.x, r1.y, r1.z, r1.w,
                    r2.x, r2.y, r2.z, r2.w, r3.x, r3.y, r3.z, r3.w};

    const float* __restrict__ Ec = E + i * 256 + d;
    float w = 0.0f;
#pragma unroll
    for (int c = 0; c < 16; c++) {
        w = fmaf(sct[c], er[c] + __ldg(Ec + c * 16), w);
    }
    g_w[t] = 0.5f * w;

    if (d == 0) {
        float s = 0.0f;
#pragma unroll
        for (int c = 0; c < 16; c++) s += sct[c];
        g_mask[i] = (s > 0.0f) ? 1.0f : 0.0f;
        float px = pos[3 * i], py = pos[3 * i + 1], pz = pos[3 * i + 2];
        g_pos4[i] = make_float4(px, py, pz, rad[i]);
        int cx = min((int)(px * INV_CELLW), NCELL_DIM - 1);
        int cy = min((int)(py * INV_CELLW), NCELL_DIM - 1);
        int cz = min((int)(pz * INV_CELLW), NCELL_DIM - 1);
        int cell = (cz << 8) | (cy << 4) | cx;
        g_cellid[i] = cell;
        int r = atomicAdd(&g_ccnt[cell], 1);
        if (r < SLOTS) {
            g_slots[cell * SLOTS + r] = i;
        } else {
            unsigned o = atomicAdd(&g_nov, 1u);
            g_ovf[o] = make_int2(cell, i);
        }
    }
}

// ---------------------------------------------------------------------------
// Heavy path, symmetric unordered form: returns base_ij * (mi + mj), where
// base_ij = (5*sigmoid(eps)+0.3)*(u^2-1)*cut. Caller sums and scales by 0.5.
// All four w/ct float4 streams issued concurrently (one L2 round).
// ---------------------------------------------------------------------------
__device__ __forceinline__ float pair_sym(float r2, float ri, float rj,
                                          float mi, float mj,
                                          int ig, int jg,
                                          const float* __restrict__ ct) {
    const float4* __restrict__ wi4 = (const float4*)(g_w + ig * NC);
    const float4* __restrict__ ci4 = (const float4*)(ct + ig * NC);
    const float4* __restrict__ wj4 = (const float4*)(g_w + jg * NC);
    const float4* __restrict__ cj4 = (const float4*)(ct + jg * NC);
    float dot = 0.0f;
#pragma unroll
    for (int q = 0; q < 4; q++) {
        float4 wi = wi4[q], ci = ci4[q], wj = wj4[q], cj = cj4[q];
        dot = fmaf(wi.x, cj.x, dot); dot = fmaf(wj.x, ci.x, dot);
        dot = fmaf(wi.y, cj.y, dot); dot = fmaf(wj.y, ci.y, dot);
        dot = fmaf(wi.z, cj.z, dot); dot = fmaf(wj.z, ci.z, dot);
        dot = fmaf(wi.w, cj.w, dot); dot = fmaf(wj.w, ci.w, dot);
    }
    float dr  = sqrtf(r2);
    float t   = R_C2 - r2;
    float poly = t * t * (R_C2 + 2.0f * r2 - 3.0f * R_ON2) * CUT_INV_DENOM;
    float cut  = (r2 < R_ON2) ? 1.0f : poly;
    float er  = 0.5f * dot;
    float eps = __fdividef(5.0f, 1.0f + __expf(-er)) + 0.3f;
    float u   = 1.0f - __expf(-ALPHA_F * (dr - (ri + rj)));
    return eps * (u * u - 1.0f) * cut * (mi + mj);
}

#define CE(a, b) { int lo = min(ids[a], ids[b]); int hi = max(ids[a], ids[b]); \
                   ids[a] = lo; ids[b] = hi; }

// ---------------------------------------------------------------------------
// Kernel 2: energy. One thread per (particle, neighbor cell). Each unordered
// pair evaluated ONCE (on the i-thread with j > i) via the symmetric form.
// 864 blocks x 128, reg-capped to keep 6 blocks/SM (single wave). Ids sorted
// ascending by a Batcher-8 register network (determinism). Fused final
// reduction + counter reset for graph replay.
// ---------------------------------------------------------------------------
__global__ __launch_bounds__(128, 6)
void energy_kernel(const float* __restrict__ ct, float* __restrict__ out) {
    __shared__ float red[128];
    __shared__ bool  is_last;

    const int t   = blockIdx.x * 128 + threadIdx.x;  // 0 .. 110591
    const int tid = threadIdx.x;
    const int i   = t / 27;
    const int r   = t - i * 27;

    const int    cid = g_cellid[i];   // these three issue in parallel
    const float4 pi  = g_pos4[i];
    const float  mi  = g_mask[i];

    const int cx = (cid & 15)        + (r % 3) - 1;
    const int cy = ((cid >> 4) & 15) + ((r / 3) % 3) - 1;
    const int cz = (cid >> 8)        + (r / 9) - 1;

    float acc = 0.0f;

    if (cx >= 0 && cx < NCELL_DIM && cy >= 0 && cy < NCELL_DIM &&
        cz >= 0 && cz < NCELL_DIM) {
        const int nc = (cz << 8) | (cy << 4) | cx;
        const int k  = g_ccnt[nc];                         // LDG
        const int4 s0 = ((const int4*)g_slots)[nc * 2];    // LDG.128 (parallel)
        const int4 s1 = ((const int4*)g_slots)[nc * 2 + 1];

        if (k > 0) {
            int ids[8] = {s0.x, s0.y, s0.z, s0.w, s1.x, s1.y, s1.z, s1.w};
#pragma unroll
            for (int u = 0; u < 8; u++)
                if (u >= k) ids[u] = 0x7fffffff;           // sentinel pad
            // Batcher odd-even 8-sort (19 compare-exchanges, registers only)
            CE(0,1) CE(2,3) CE(4,5) CE(6,7)
            CE(0,2) CE(1,3) CE(4,6) CE(5,7)
            CE(1,2) CE(5,6)
            CE(0,4) CE(1,5) CE(2,6) CE(3,7)
            CE(2,4) CE(3,5)
            CE(1,2) CE(3,4) CE(5,6)
#pragma unroll
            for (int u = 0; u < 8; u++) {
                int j = ids[u];
                if (j > i && j < NPART) {                  // once per pair
                    float4 pj = g_pos4[j];
                    float dx = pi.x - pj.x, dy = pi.y - pj.y, dz = pi.z - pj.z;
                    float r2 = fmaf(dx, dx, fmaf(dy, dy, dz * dz));
                    if (r2 < R_C2) {
                        float mj = g_mask[j];
                        acc += pair_sym(r2, pi.w, pj.w, mi, mj, i, j, ct);
                    }
                }
            }
            if (k > SLOTS) {
                // correct (never-expected) overflow path, ascending by id
                unsigned nov = g_nov;
                int last = -1;
                for (int m = 0; m < k - SLOTS; m++) {
                    int best = 0x7fffffff;
                    for (unsigned u = 0; u < nov; u++) {
                        int2 e = g_ovf[u];
                        if (e.x == nc && e.y > last && e.y < best) best = e.y;
                    }
                    if (best == 0x7fffffff) break;
                    last = best;
                    if (best <= i) continue;
                    float4 pj = g_pos4[best];
                    float dx = pi.x - pj.x, dy = pi.y - pj.y, dz = pi.z - pj.z;
                    float r2 = fmaf(dx, dx, fmaf(dy, dy, dz * dz));
                    if (r2 < R_C2) {
                        float mj = g_mask[best];
                        acc += pair_sym(r2, pi.w, pj.w, mi, mj, i, best, ct);
                    }
                }
            }
        }
    }

    // deterministic block tree-reduce (128 threads)
    red[tid] = acc;
    __syncthreads();
#pragma unroll
    for (int s = 64; s > 0; s >>= 1) {
        if (tid < s) red[tid] += red[tid + s];
        __syncthreads();
    }

    if (tid == 0) {
        g_part[blockIdx.x] = red[0];
        __threadfence();
        unsigned int done = atomicAdd(&g_count, 1u);
        is_last = (done == EBLOCKS - 1);
    }
    __syncthreads();

    if (is_last) {
        // deterministic final reduction of 864 partials (fixed order)
        float v = 0.0f;
#pragma unroll
        for (int q = 0; q < 7; q++) {
            int idx = tid + q * 128;
            if (idx < EBLOCKS) v += g_part[idx];
        }
        red[tid] = v;
        __syncthreads();
#pragma unroll
        for (int s = 64; s > 0; s >>= 1) {
            if (tid < s) red[tid] += red[tid + s];
            __syncthreads();
        }
        if (tid == 0) {
            out[0] = 0.5f * red[0];
            g_count = 0;
            g_nov   = 0;
        }
        // reset per-cell counts for the next graph replay
        for (int c = tid; c < NCELLS; c += 128) g_ccnt[c] = 0;
    }
}

// ---------------------------------------------------------------------------
// Launch. Inputs (metadata order): position (N*3), celltype (N*16),
// epsilon (N*256), radius (N). Output: scalar float.
// ---------------------------------------------------------------------------
extern "C" void kernel_launch(void* const* d_in, const int* in_sizes, int n_in,
                              void* d_out, int out_size) {
    const float* pos = (const float*)d_in[0];
    const float* ct  = (const float*)d_in[1];
    const float* E   = (const float*)d_in[2];
    const float* rad = (const float*)d_in[3];
    float* out = (float*)d_out;

    prep_kernel<<<NPART * NC / 128, 128>>>(pos, ct, E, rad);
    energy_kernel<<<EBLOCKS, 128>>>(ct, out);
}

// round 12
// speedup vs baseline: 1.8427x; 1.0259x over previous
#include <cuda_runtime.h>
#include <math.h>

#define NPART 4096
#define NC 16

#define R_ON2  (1.7f * 1.7f)       /* 2.89  */
#define R_C2   (4.0f)              /* 2.0^2 */
#define CUT_INV_DENOM (1.0f / ((R_C2 - R_ON2) * (R_C2 - R_ON2) * (R_C2 - R_ON2)))
#define ALPHA_F 2.8f

#define NCELL_DIM 16
#define NCELLS (NCELL_DIM * NCELL_DIM * NCELL_DIM)   /* 4096 */
#define INV_CELLW 0.4f                               /* 1 / 2.5 */

#define SLOTS 8                                      /* direct-map width */
#define TPP 14                                       /* home + 13 forward cells */
#define EBLOCKS (NPART * TPP / 128)                  /* 448 */

// scratch (no allocations; zero-initialized at load; counters reset by the
// last energy block -> graph replays see identical initial state)
__device__ float  g_wc[NPART * 32];   // per-particle 128B record: w[16] | ct[16]
__device__ float4 g_pos4[NPART];      // x,y,z,radius
__device__ int    g_cellid[NPART];    // cell | (mask << 12)
__device__ int    g_ccnt[NCELLS];     // per-cell member count
__device__ int    g_slots[NCELLS * SLOTS];  // (j<<1)|mask_j per member
__device__ int2   g_ovf[NPART];       // overflow (cell, (j<<1)|m); ~never used
__device__ unsigned int g_nov;        // overflow count
__device__ float  g_part[EBLOCKS];
__device__ unsigned int g_count;      // last-block counter

// 13 forward neighbor-cell offsets: (dz>0) || (dz==0 && dy>0) || (dz==0&&dy==0&&dx>0)
__device__ __constant__ signed char FWD[13][3] = {
    { 1, 0, 0},
    {-1, 1, 0}, { 0, 1, 0}, { 1, 1, 0},
    {-1,-1, 1}, { 0,-1, 1}, { 1,-1, 1},
    {-1, 0, 1}, { 0, 0, 1}, { 1, 0, 1},
    {-1, 1, 1}, { 0, 1, 1}, { 1, 1, 1},
};

// ---------------------------------------------------------------------------
// Kernel 1: per-particle contraction w_i = ct_i^T E_sym_i, packed record,
// mask packing, cell binning. One thread per (particle, dim).
// ---------------------------------------------------------------------------
__global__ __launch_bounds__(128)
void prep_kernel(const float* __restrict__ pos,
                 const float* __restrict__ ct,
                 const float* __restrict__ E,
                 const float* __restrict__ rad) {
    const int t = blockIdx.x * 128 + threadIdx.x;   // 0 .. 65535
    const int i = t >> 4;
    const int d = t & 15;

    const float4* __restrict__ ct4 = (const float4*)(ct + i * NC);
    float4 c0 = ct4[0], c1 = ct4[1], c2 = ct4[2], c3 = ct4[3];
    float sct[16] = {c0.x, c0.y, c0.z, c0.w, c1.x, c1.y, c1.z, c1.w,
                     c2.x, c2.y, c2.z, c2.w, c3.x, c3.y, c3.z, c3.w};

    const float4* __restrict__ Er4 = (const float4*)(E + i * 256 + d * NC);
    float4 r0 = Er4[0], r1 = Er4[1], r2 = Er4[2], r3 = Er4[3];
    float er[16] = {r0.x, r0.y, r0.z, r0.w, r1.x, r1.y, r1.z, r1.w,
                    r2.x, r2.y, r2.z, r2.w, r3.x, r3.y, r3.z, r3.w};

    const float* __restrict__ Ec = E + i * 256 + d;
    float w = 0.0f;
#pragma unroll
    for (int c = 0; c < 16; c++) {
        w = fmaf(sct[c], er[c] + __ldg(Ec + c * 16), w);
    }
    g_wc[i * 32 + d]      = 0.5f * w;   // w half of the record
    g_wc[i * 32 + 16 + d] = sct[d];     // ct half of the record

    if (d == 0) {
        float s = 0.0f;
#pragma unroll
        for (int c = 0; c < 16; c++) s += sct[c];
        int m = (s > 0.0f) ? 1 : 0;
        float px = pos[3 * i], py = pos[3 * i + 1], pz = pos[3 * i + 2];
        g_pos4[i] = make_float4(px, py, pz, rad[i]);
        int cx = min((int)(px * INV_CELLW), NCELL_DIM - 1);
        int cy = min((int)(py * INV_CELLW), NCELL_DIM - 1);
        int cz = min((int)(pz * INV_CELLW), NCELL_DIM - 1);
        int cell = (cz << 8) | (cy << 4) | cx;
        g_cellid[i] = cell | (m << 12);
        int v = (i << 1) | m;
        int r = atomicAdd(&g_ccnt[cell], 1);
        if (r < SLOTS) {
            g_slots[cell * SLOTS + r] = v;
        } else {
            unsigned o = atomicAdd(&g_nov, 1u);
            g_ovf[o] = make_int2(cell, v);
        }
    }
}

// ---------------------------------------------------------------------------
// Heavy path, symmetric unordered form: base_ij * (mi + mj). Each side's
// w|ct record is ONE aligned 128B line (8 LDG.128 over 2 lines total).
// ---------------------------------------------------------------------------
__device__ __forceinline__ float pair_sym(float r2, float ri, float rj,
                                          float mi, float mj,
                                          int ig, int jg) {
    const float4* __restrict__ ri4 = (const float4*)(g_wc + ig * 32);
    const float4* __restrict__ rj4 = (const float4*)(g_wc + jg * 32);
    float dot = 0.0f;
#pragma unroll
    for (int q = 0; q < 4; q++) {
        float4 wi = ri4[q], ci = ri4[q + 4];   // w: q0-3, ct: q4-7
        float4 wj = rj4[q], cj = rj4[q + 4];
        dot = fmaf(wi.x, cj.x, dot); dot = fmaf(wj.x, ci.x, dot);
        dot = fmaf(wi.y, cj.y, dot); dot = fmaf(wj.y, ci.y, dot);
        dot = fmaf(wi.z, cj.z, dot); dot = fmaf(wj.z, ci.z, dot);
        dot = fmaf(wi.w, cj.w, dot); dot = fmaf(wj.w, ci.w, dot);
    }
    float dr  = sqrtf(r2);
    float t   = R_C2 - r2;
    float poly = t * t * (R_C2 + 2.0f * r2 - 3.0f * R_ON2) * CUT_INV_DENOM;
    float cut  = (r2 < R_ON2) ? 1.0f : poly;
    float er  = 0.5f * dot;
    float eps = __fdividef(5.0f, 1.0f + __expf(-er)) + 0.3f;
    float u   = 1.0f - __expf(-ALPHA_F * (dr - (ri + rj)));
    return eps * (u * u - 1.0f) * cut * (mi + mj);
}

#define CE(a, b) { int lo = min(ids[a], ids[b]); int hi = max(ids[a], ids[b]); \
                   ids[a] = lo; ids[b] = hi; }

// ---------------------------------------------------------------------------
// Kernel 2: energy. One thread per (particle, {home + 13 forward cells}).
// Home cell uses j > i; forward cells own each cross-cell pair uniquely, so
// no filter. 448 blocks x 128. Slot values (j<<1)|m sorted ascending by a
// Batcher-8 register network (order is by j; determinism). Fused final
// reduction + counter reset for graph replay.
// ---------------------------------------------------------------------------
__global__ __launch_bounds__(128, 6)
void energy_kernel(float* __restrict__ out) {
    __shared__ float red[128];
    __shared__ bool  is_last;

    const int t   = blockIdx.x * 128 + threadIdx.x;  // 0 .. 57343
    const int tid = threadIdx.x;
    const int i   = t / TPP;
    const int r   = t - i * TPP;

    const int    cid = g_cellid[i];   // parallel loads
    const float4 pi  = g_pos4[i];
    const float  mi  = (float)((cid >> 12) & 1);

    int cx = cid & 15;
    int cy = (cid >> 4) & 15;
    int cz = (cid >> 8) & 15;
    if (r > 0) {
        cx += FWD[r - 1][0];
        cy += FWD[r - 1][1];
        cz += FWD[r - 1][2];
    }

    float acc = 0.0f;

    if (cx >= 0 && cx < NCELL_DIM && cy >= 0 && cy < NCELL_DIM &&
        cz >= 0 && cz < NCELL_DIM) {
        const int nc = (cz << 8) | (cy << 4) | cx;
        const int k  = g_ccnt[nc];                         // LDG
        const int4 s0 = ((const int4*)g_slots)[nc * 2];    // LDG.128 (parallel)
        const int4 s1 = ((const int4*)g_slots)[nc * 2 + 1];

        if (k > 0) {
            int ids[8] = {s0.x, s0.y, s0.z, s0.w, s1.x, s1.y, s1.z, s1.w};
#pragma unroll
            for (int u = 0; u < 8; u++)
                if (u >= k) ids[u] = 0x7fffffff;           // sentinel pad
            // Batcher odd-even 8-sort (19 compare-exchanges, registers only)
            CE(0,1) CE(2,3) CE(4,5) CE(6,7)
            CE(0,2) CE(1,3) CE(4,6) CE(5,7)
            CE(1,2) CE(5,6)
            CE(0,4) CE(1,5) CE(2,6) CE(3,7)
            CE(2,4) CE(3,5)
            CE(1,2) CE(3,4) CE(5,6)
#pragma unroll
            for (int u = 0; u < 8; u++) {
                int v = ids[u];
                int j = v >> 1;
                // home cell (r==0): j>i once-per-pair; forward cells: all j
                if (j < NPART && (r > 0 || j > i)) {
                    float4 pj = g_pos4[j];
                    float dx = pi.x - pj.x, dy = pi.y - pj.y, dz = pi.z - pj.z;
                    float r2 = fmaf(dx, dx, fmaf(dy, dy, dz * dz));
                    if (r2 < R_C2) {
                        float mj = (float)(v & 1);
                        acc += pair_sym(r2, pi.w, pj.w, mi, mj, i, j);
                    }
                }
            }
            if (k > SLOTS) {
                // correct (never-expected) overflow path, ascending by id
                unsigned nov = g_nov;
                int last = -1;
                for (int m = 0; m < k - SLOTS; m++) {
                    int bestv = 0x7fffffff;
                    for (unsigned u = 0; u < nov; u++) {
                        int2 e = g_ovf[u];
                        if (e.x == nc && e.y > last && e.y < bestv) bestv = e.y;
                    }
                    if (bestv == 0x7fffffff) break;
                    last = bestv;
                    int j = bestv >> 1;
                    if (!(r > 0 || j > i)) continue;
                    float4 pj = g_pos4[j];
                    float dx = pi.x - pj.x, dy = pi.y - pj.y, dz = pi.z - pj.z;
                    float r2 = fmaf(dx, dx, fmaf(dy, dy, dz * dz));
                    if (r2 < R_C2) {
                        float mj = (float)(bestv & 1);
                        acc += pair_sym(r2, pi.w, pj.w, mi, mj, i, j);
                    }
                }
            }
        }
    }

    // deterministic block tree-reduce (128 threads)
    red[tid] = acc;
    __syncthreads();
#pragma unroll
    for (int s = 64; s > 0; s >>= 1) {
        if (tid < s) red[tid] += red[tid + s];
        __syncthreads();
    }

    if (tid == 0) {
        g_part[blockIdx.x] = red[0];
        __threadfence();
        unsigned int done = atomicAdd(&g_count, 1u);
        is_last = (done == EBLOCKS - 1);
    }
    __syncthreads();

    if (is_last) {
        // deterministic final reduction of 448 partials (fixed order)
        float v = 0.0f;
#pragma unroll
        for (int q = 0; q < 4; q++) {
            int idx = tid + q * 128;
            if (idx < EBLOCKS) v += g_part[idx];
        }
        red[tid] = v;
        __syncthreads();
#pragma unroll
        for (int s = 64; s > 0; s >>= 1) {
            if (tid < s) red[tid] += red[tid + s];
            __syncthreads();
        }
        if (tid == 0) {
            out[0] = 0.5f * red[0];
            g_count = 0;
            g_nov   = 0;
        }
        // reset per-cell counts for the next graph replay
        for (int c = tid; c < NCELLS; c += 128) g_ccnt[c] = 0;
    }
}

// ---------------------------------------------------------------------------
// Launch. Inputs (metadata order): position (N*3), celltype (N*16),
// epsilon (N*256), radius (N). Output: scalar float.
// ---------------------------------------------------------------------------
extern "C" void kernel_launch(void* const* d_in, const int* in_sizes, int n_in,
                              void* d_out, int out_size) {
    const float* pos = (const float*)d_in[0];
    const float* ct  = (const float*)d_in[1];
    const float* E   = (const float*)d_in[2];
    const float* rad = (const float*)d_in[3];
    float* out = (float*)d_out;

    prep_kernel<<<NPART * NC / 128, 128>>>(pos, ct, E, rad);
    energy_kernel<<<EBLOCKS, 128>>>(out);
}